// round 15
// baseline (speedup 1.0000x reference)
#include <cuda_runtime.h>
#include <cuda_bf16.h>
#include <cstdint>

// HopfOscillatorModule, round 15: fragment-direct HMMA, 2-term bf16 split.
//   [P|Q](row) = [x|y](row) . M (64x64 const).
//   A = x|y split (hi+lo) IN REGISTERS; B = M rounded to single bf16 in SMEM.
//   (A_hi + A_lo) . B_bf16 : only B's rounding (~2^-10) is dropped ->
//   predicted rel_err ~1e-5..1e-4, vs 1e-3 threshold.
// k and n are permuted (map16) so each thread's A-fragments / D-columns fall
// on 8 contiguous oscillators it loads itself via LDG.128. No A tiles, no psi
// cache, 16 ldm4 + 32 MMA per warp. sincos computed once, reused in epilogue.

#define NOSC 32
#define TILE_ROWS 128
#define TWO_PI 6.283185307179586f

typedef unsigned int u32;

#define B_STRIDE 144

__device__ __align__(16) unsigned char g_Bhi[64 * B_STRIDE];
__device__ __align__(16) float g_K0[NOSC];
__device__ __align__(16) float g_K1[NOSC];
__device__ __align__(16) float g_K2[NOSC];
__device__ __align__(16) float g_tpv[NOSC];

__device__ __forceinline__ float sigmoidf_(float x) { return 1.0f / (1.0f + expf(-x)); }

// fragment-order map within a 16-block: w = 2t+d (u=0) or 8+2t+d (u=1) -> 4t+2u+d
__device__ __forceinline__ int map16(int w) {
    int u = (w >> 3) & 1, t = (w >> 1) & 3, d = w & 1;
    return 4 * t + 2 * u + d;
}

// ---------------- setup: 32 CTAs, one B-entry per thread ----------------
__global__ void hopf_setup_kernel(const float* __restrict__ v, const float* __restrict__ b,
                                  const float* __restrict__ c, const float* __restrict__ w,
                                  const float* __restrict__ phi)
{
    int tid = threadIdx.x;
    if (blockIdx.x == 0 && tid < NOSC) {
        float va = 5.0f * sigmoidf_(v[tid]);
        float ba = 2.0f * sigmoidf_(b[tid]);
        float ca = 10.0f * sigmoidf_(c[tid]);
        float K1 = 0.25f * ca * ca;
        g_K0[tid] = K1 * ba;
        g_K1[tid] = K1;
        g_K2[tid] = ca;
        g_tpv[tid] = TWO_PI * va;
    }
    int e = blockIdx.x * 128 + tid;            // 0..4095
    int n = e >> 6, k = e & 63;
    // k -> (is_x, j) with fragment permutation
    int ks = k >> 4;
    int j = ((ks & 1) << 4) + map16(k & 15);
    bool is_x = (ks < 2);
    // n -> (P/Q, oscillator i) with the same permutation
    int p = n >> 5;
    int m = n & 31;
    int i = ((m >> 4) << 4) + map16(m & 15);
    int flat = 32 * i + j;                     // index into zero-diag 32x32
    float A = 0.0f, Bc = 0.0f;
    if (flat != 1023) {
        // _zero_diag: z = concat([zeros(31,1), P],1).ravel() ++ [0] -> (32,32)
        int t = flat / 33, pos = flat % 33;
        if (pos != 0) {
            float wa = sigmoidf_(w[t * 32 + pos - 1]);            // W_MAX = 1
            float pa = TWO_PI * sigmoidf_(phi[t * 32 + pos - 1]);
            float sp, cp;
            sincosf(pa, &sp, &cp);
            A = wa * cp;
            Bc = wa * sp;
        }
    }
    float Mf;
    if (p == 0) Mf = is_x ? A : -Bc;     // P part
    else        Mf = is_x ? Bc : A;      // Q part
    *(__nv_bfloat16*)(g_Bhi + n * B_STRIDE + k * 2) = __float2bfloat16_rn(Mf);
}

// ---------------- ptx helpers ----------------
__device__ __forceinline__ u32 smem_u32(const void* p) {
    u32 a;
    asm("{ .reg .u64 t; cvta.to.shared.u64 t, %1; cvt.u32.u64 %0, t; }" : "=r"(a) : "l"(p));
    return a;
}
__device__ __forceinline__ void ldm4(u32* r, u32 addr) {
    asm volatile("ldmatrix.sync.aligned.m8n8.x4.shared.b16 {%0,%1,%2,%3}, [%4];"
                 : "=r"(r[0]), "=r"(r[1]), "=r"(r[2]), "=r"(r[3]) : "r"(addr));
}
__device__ __forceinline__ void mma16816(float* d, u32 a0, u32 a1, u32 a2, u32 a3,
                                         u32 b0, u32 b1) {
    asm volatile(
        "mma.sync.aligned.m16n8k16.row.col.f32.bf16.bf16.f32 "
        "{%0,%1,%2,%3}, {%4,%5,%6,%7}, {%8,%9}, {%0,%1,%2,%3};"
        : "+f"(d[0]), "+f"(d[1]), "+f"(d[2]), "+f"(d[3])
        : "r"(a0), "r"(a1), "r"(a2), "r"(a3), "r"(b0), "r"(b1));
}

// ---------------- main kernel ----------------
__global__ __launch_bounds__(256, 2)
void hopf_kernel(const float* __restrict__ in, float* __restrict__ out, int nrows)
{
    __shared__ __align__(16) unsigned char sBhi[64 * B_STRIDE];

    int tid = threadIdx.x;
    int lane = tid & 31;
    int wid = tid >> 5;
    u32 sbh = smem_u32(sBhi);

    // Stage constant B tile (LDG->STS); barrier comes AFTER the prologue.
    {
        const uint4* gh = (const uint4*)g_Bhi;
        uint4* sh = (uint4*)sBhi;
        for (int i = tid; i < (64 * B_STRIDE) / 16; i += 256)
            sh[i] = gh[i];
    }

    int g = lane >> 2;
    int t = lane & 3;
    int base = blockIdx.x * TILE_ROWS;
    int mrow = wid * 16;

    // sincos + fragment registers. [r] = row g / g+8; [h] = j-chunk 16h+4t.
    float S[2][2][4], C[2][2][4];
    u32 XH[2][4], XL[2][4], YH[2][4], YL[2][4];   // [r][pair]: pairs 2h, 2h+1

    // ---- prologue: LDG.128 -> sincos -> fragments + r_d / r_d_dot stores ----
#pragma unroll
    for (int r = 0; r < 2; r++) {
        int row = base + mrow + g + 8 * r;
        bool ok = row < nrows;
        const float* ip = in + (size_t)row * 96;
        float* op = out + (size_t)row * 96;
#pragma unroll
        for (int h = 0; h < 2; h++) {
            int j0 = 16 * h + 4 * t;
            float4 p4 = ok ? *(const float4*)(ip + j0) : make_float4(0.f, 0.f, 0.f, 0.f);
            float4 r4 = ok ? *(const float4*)(ip + 32 + j0) : make_float4(0.f, 0.f, 0.f, 0.f);
            float4 d4 = ok ? *(const float4*)(ip + 64 + j0) : make_float4(0.f, 0.f, 0.f, 0.f);
            float4 K0 = ((const float4*)g_K0)[4 * h + t];
            float4 K1 = ((const float4*)g_K1)[4 * h + t];
            float4 K2 = ((const float4*)g_K2)[4 * h + t];
            float px[4] = {p4.x, p4.y, p4.z, p4.w};
            float rx[4] = {r4.x, r4.y, r4.z, r4.w};
            float dx[4] = {d4.x, d4.y, d4.z, d4.w};
            float k0a[4] = {K0.x, K0.y, K0.z, K0.w};
            float k1a[4] = {K1.x, K1.y, K1.z, K1.w};
            float k2a[4] = {K2.x, K2.y, K2.z, K2.w};
            float X[4], Y[4], F[4];
#pragma unroll
            for (int e = 0; e < 4; e++) {
                float s, c;
                __sincosf(px[e], &s, &c);
                S[r][h][e] = s;
                C[r][h][e] = c;
                X[e] = rx[e] * s;
                Y[e] = rx[e] * c;
                F[e] = fmaf(-k2a[e], dx[e], fmaf(-k1a[e], rx[e], k0a[e]));
            }
            __nv_bfloat162 xh0 = __floats2bfloat162_rn(X[0], X[1]);
            __nv_bfloat162 xh1 = __floats2bfloat162_rn(X[2], X[3]);
            __nv_bfloat162 yh0 = __floats2bfloat162_rn(Y[0], Y[1]);
            __nv_bfloat162 yh1 = __floats2bfloat162_rn(Y[2], Y[3]);
            __nv_bfloat162 xl0 = __floats2bfloat162_rn(X[0] - __bfloat162float(xh0.x),
                                                       X[1] - __bfloat162float(xh0.y));
            __nv_bfloat162 xl1 = __floats2bfloat162_rn(X[2] - __bfloat162float(xh1.x),
                                                       X[3] - __bfloat162float(xh1.y));
            __nv_bfloat162 yl0 = __floats2bfloat162_rn(Y[0] - __bfloat162float(yh0.x),
                                                       Y[1] - __bfloat162float(yh0.y));
            __nv_bfloat162 yl1 = __floats2bfloat162_rn(Y[2] - __bfloat162float(yh1.x),
                                                       Y[3] - __bfloat162float(yh1.y));
            XH[r][2 * h] = *(u32*)&xh0;
            XH[r][2 * h + 1] = *(u32*)&xh1;
            XL[r][2 * h] = *(u32*)&xl0;
            XL[r][2 * h + 1] = *(u32*)&xl1;
            YH[r][2 * h] = *(u32*)&yh0;
            YH[r][2 * h + 1] = *(u32*)&yh1;
            YL[r][2 * h] = *(u32*)&yl0;
            YL[r][2 * h + 1] = *(u32*)&yl1;
            if (ok) {
                *(float4*)(op + 32 + j0) = d4;                                  // r_d
                *(float4*)(op + 64 + j0) = make_float4(F[0], F[1], F[2], F[3]); // r_d_dot
            }
        }
    }
    __syncthreads();   // B tile ready (staging overlapped with prologue)

    // ---- MMA: A (hi+lo) from registers, single-bf16 B via ldmatrix ----
    float acc[8][4];
#pragma unroll
    for (int nt = 0; nt < 8; nt++)
#pragma unroll
        for (int e = 0; e < 4; e++) acc[nt][e] = 0.0f;

    int lrow = lane & 15;
    int lhalf = lane >> 4;

#pragma unroll
    for (int ks = 0; ks < 4; ks++) {
        u32 kb = ks * 32 + lhalf * 16;
        int p = (ks & 1) * 2;              // fragment pair base for this chunk
        u32 ah0, ah1, ah2, ah3, al0, al1, al2, al3;
        if (ks < 2) {
            ah0 = XH[0][p]; ah1 = XH[1][p]; ah2 = XH[0][p + 1]; ah3 = XH[1][p + 1];
            al0 = XL[0][p]; al1 = XL[1][p]; al2 = XL[0][p + 1]; al3 = XL[1][p + 1];
        } else {
            ah0 = YH[0][p]; ah1 = YH[1][p]; ah2 = YH[0][p + 1]; ah3 = YH[1][p + 1];
            al0 = YL[0][p]; al1 = YL[1][p]; al2 = YL[0][p + 1]; al3 = YL[1][p + 1];
        }
        u32 bh[4][4];
#pragma unroll
        for (int nb = 0; nb < 4; nb++)
            ldm4(bh[nb], sbh + (u32)((nb * 16 + lrow) * B_STRIDE) + kb);
#pragma unroll
        for (int nb = 0; nb < 4; nb++) {
            mma16816(acc[2 * nb + 0], ah0, ah1, ah2, ah3, bh[nb][0], bh[nb][2]);
            mma16816(acc[2 * nb + 1], ah0, ah1, ah2, ah3, bh[nb][1], bh[nb][3]);
            mma16816(acc[2 * nb + 0], al0, al1, al2, al3, bh[nb][0], bh[nb][2]);
            mma16816(acc[2 * nb + 1], al0, al1, al2, al3, bh[nb][1], bh[nb][3]);
        }
    }

    // ---- epilogue: psi_dot from fragments + register sincos -> STG.128 ----
    // Thread's cols land on i = 16h+4t+e: P = acc[2h+(e>>1)], Q = acc[4+2h+(e>>1)],
    // element (e&1) + 2r.
#pragma unroll
    for (int r = 0; r < 2; r++) {
        int row = base + mrow + g + 8 * r;
        if (row < nrows) {
            float* op = out + (size_t)row * 96;
#pragma unroll
            for (int h = 0; h < 2; h++) {
                float4 tp = ((const float4*)g_tpv)[4 * h + t];
                float tpa[4] = {tp.x, tp.y, tp.z, tp.w};
                float v[4];
#pragma unroll
                for (int e = 0; e < 4; e++) {
                    int cp = 2 * h + (e >> 1);
                    int el = (e & 1) + 2 * r;
                    v[e] = fmaf(C[r][h][e], acc[cp][el],
                                fmaf(-S[r][h][e], acc[cp + 4][el], tpa[e]));
                }
                *(float4*)(op + 16 * h + 4 * t) = make_float4(v[0], v[1], v[2], v[3]);
            }
        }
    }
}

extern "C" void kernel_launch(void* const* d_in, const int* in_sizes, int n_in,
                              void* d_out, int out_size)
{
    const float* states = (const float*)d_in[0];
    const float* v = (const float*)d_in[1];
    const float* b = (const float*)d_in[2];
    const float* c = (const float*)d_in[3];
    const float* w = (const float*)d_in[4];
    const float* phi = (const float*)d_in[5];
    int nrows = in_sizes[0] / 96;

    hopf_setup_kernel<<<32, 128>>>(v, b, c, w, phi);

    int grid = (nrows + TILE_ROWS - 1) / TILE_ROWS;
    hopf_kernel<<<grid, 256>>>(states, (float*)d_out, nrows);
}